// round 1
// baseline (speedup 1.0000x reference)
#include <cuda_runtime.h>

#define NN 100000
#define EE 1250000
#define HH 64
#define BN_EPS 1e-5f

// ---------------- scratch (static device arrays; no allocation) ----------------
__device__ float g_h0[NN * HH];   // post-fc activation ("last" residual source)
__device__ float g_h1[NN * HH];   // layer-0 output
__device__ float g_hw[NN * HH];   // transformed features, pre-scaled by dis[row]
__device__ float g_dis[NN];       // deg^-1/2 (deg includes self loop)
__device__ int   g_cnt[NN];       // in-degree histogram (without self loop)
__device__ int   g_off[NN + 1];   // CSR offsets
__device__ int   g_cur[NN];       // CSR fill cursors
__device__ int   g_csr[EE];       // CSR source indices
__device__ int   g_part[128];     // scan partials

// ---------------- CSR build ----------------
__global__ void zero_k() {
    int i = blockIdx.x * blockDim.x + threadIdx.x;
    if (i < NN) { g_cnt[i] = 0; g_cur[i] = 0; }
}

__global__ void hist_k(const int* __restrict__ dst) {
    int i = blockIdx.x * blockDim.x + threadIdx.x;
    if (i < EE) atomicAdd(&g_cnt[dst[i]], 1);
}

__global__ void scan1_k() {
    __shared__ int sh[1024];
    int tid = threadIdx.x;
    int i = blockIdx.x * 1024 + tid;
    int v = (i < NN) ? g_cnt[i] : 0;
    sh[tid] = v;
    __syncthreads();
    #pragma unroll
    for (int d = 1; d < 1024; d <<= 1) {
        int t = (tid >= d) ? sh[tid - d] : 0;
        __syncthreads();
        sh[tid] += t;
        __syncthreads();
    }
    if (i < NN) g_off[i] = sh[tid];          // within-block inclusive scan
    if (tid == 1023) g_part[blockIdx.x] = sh[1023];
}

__global__ void scan2_k() {
    __shared__ int sh[128];
    int tid = threadIdx.x;
    const int nb = (NN + 1023) / 1024;       // 98
    int v = (tid < nb) ? g_part[tid] : 0;
    sh[tid] = v;
    __syncthreads();
    #pragma unroll
    for (int d = 1; d < 128; d <<= 1) {
        int t = (tid >= d) ? sh[tid - d] : 0;
        __syncthreads();
        sh[tid] += t;
        __syncthreads();
    }
    g_part[tid] = sh[tid] - v;               // exclusive scan of block totals
}

__global__ void scan3_k() {
    int i = blockIdx.x * blockDim.x + threadIdx.x;
    if (i < NN) {
        int c = g_cnt[i];
        g_off[i] = g_off[i] - c + g_part[i >> 10];   // exclusive global offsets
        g_dis[i] = rsqrtf((float)(c + 1));           // +1 self loop
    }
    if (i == 0) g_off[NN] = EE;
}

__global__ void fill_k(const int* __restrict__ src, const int* __restrict__ dst) {
    int i = blockIdx.x * blockDim.x + threadIdx.x;
    if (i < EE) {
        int d = dst[i];
        int p = g_off[d] + atomicAdd(&g_cur[d], 1);
        g_csr[p] = src[i];
    }
}

// ---------------- GEMM: out[64-wide] = A[row, K] @ W[K, 64] (+ epilogue) ----------------
// MODE 0: fc epilogue  -> relu(bn0(acc + fc_b))
// MODE 1: conv epilogue -> acc * dis[row]   (pre-scale for aggregation)
template <int KDIM, int MODE>
__global__ __launch_bounds__(256)
void gemm_k(const float* __restrict__ A, const float* __restrict__ W,
            float* __restrict__ out,
            const float* __restrict__ fcb, const float* __restrict__ bng,
            const float* __restrict__ bnb, const float* __restrict__ bnm,
            const float* __restrict__ bnv)
{
    __shared__ __align__(16) float ws[64 * 64];   // W chunk [k][c], 16KB
    __shared__ __align__(16) float xs[64 * 68];   // A tile, padded stride 68

    int tid = threadIdx.x;
    int row0 = blockIdx.x * 64;
    int tx = tid & 15, ty = tid >> 4;
    int r0 = ty * 4, c0 = tx * 4;

    float acc[4][4];
    #pragma unroll
    for (int i = 0; i < 4; i++)
        #pragma unroll
        for (int j = 0; j < 4; j++) acc[i][j] = 0.f;

    #pragma unroll
    for (int kb = 0; kb < KDIM / 64; kb++) {
        // load W chunk (64x64 floats = 1024 float4)
        #pragma unroll
        for (int i = 0; i < 4; i++) {
            int idx = tid + i * 256;
            ((float4*)ws)[idx] = ((const float4*)(W + kb * 64 * HH))[idx];
        }
        // load A tile chunk (64 rows x 64 cols)
        #pragma unroll
        for (int i = 0; i < 4; i++) {
            int idx = tid + i * 256;      // float4 units; 16 per row
            int r = idx >> 4, c4 = idx & 15;
            int grow = row0 + r;
            float4 v = make_float4(0.f, 0.f, 0.f, 0.f);
            if (grow < NN)
                v = *(const float4*)&A[(long)grow * KDIM + kb * 64 + c4 * 4];
            *(float4*)&xs[r * 68 + c4 * 4] = v;
        }
        __syncthreads();

        for (int k = 0; k < 64; k++) {
            float4 b = *(const float4*)&ws[k * HH + c0];
            #pragma unroll
            for (int i = 0; i < 4; i++) {
                float a = xs[(r0 + i) * 68 + k];
                acc[i][0] += a * b.x;
                acc[i][1] += a * b.y;
                acc[i][2] += a * b.z;
                acc[i][3] += a * b.w;
            }
        }
        __syncthreads();
    }

    if (MODE == 0) {
        float sc[4], mm[4], bb[4], fb[4];
        #pragma unroll
        for (int j = 0; j < 4; j++) {
            int c = c0 + j;
            sc[j] = bng[c] * rsqrtf(bnv[c] + BN_EPS);
            mm[j] = bnm[c];
            bb[j] = bnb[c];
            fb[j] = fcb[c];
        }
        #pragma unroll
        for (int i = 0; i < 4; i++) {
            int grow = row0 + r0 + i;
            if (grow < NN) {
                float4 o;
                o.x = fmaxf((acc[i][0] + fb[0] - mm[0]) * sc[0] + bb[0], 0.f);
                o.y = fmaxf((acc[i][1] + fb[1] - mm[1]) * sc[1] + bb[1], 0.f);
                o.z = fmaxf((acc[i][2] + fb[2] - mm[2]) * sc[2] + bb[2], 0.f);
                o.w = fmaxf((acc[i][3] + fb[3] - mm[3]) * sc[3] + bb[3], 0.f);
                *(float4*)&out[(long)grow * HH + c0] = o;
            }
        }
    } else {
        #pragma unroll
        for (int i = 0; i < 4; i++) {
            int grow = row0 + r0 + i;
            if (grow < NN) {
                float dn = g_dis[grow];
                float4 o = make_float4(acc[i][0] * dn, acc[i][1] * dn,
                                       acc[i][2] * dn, acc[i][3] * dn);
                *(float4*)&out[(long)grow * HH + c0] = o;
            }
        }
    }
}

// ---------------- aggregation: gather over CSR + bn + relu + residual ----------------
// hw rows are pre-scaled by dis[row]. For node n:
//   agg = dis[n] * ( hw'[n]  +  sum_{e in in(n)} hw'[src_e] ) + conv_b
//   out = relu(bn(agg)) + last
__global__ __launch_bounds__(256)
void agg_k(const float* __restrict__ hw,
           const float* __restrict__ cb, const float* __restrict__ bng,
           const float* __restrict__ bnb, const float* __restrict__ bnm,
           const float* __restrict__ bnv, const float* __restrict__ last,
           float* __restrict__ out)
{
    int gid = blockIdx.x * blockDim.x + threadIdx.x;
    int node = gid >> 4;
    if (node >= NN) return;
    int c4 = gid & 15;                       // this thread owns features [4*c4, 4*c4+4)

    const float4* hw4 = (const float4*)hw;
    float4 acc = hw4[node * 16 + c4];        // self-loop term (already x dis)
    int s = g_off[node], e = g_off[node + 1];
    for (int i = s; i < e; i++) {
        int u = g_csr[i];                    // broadcast within half-warp
        float4 v = hw4[u * 16 + c4];         // coalesced 256B across half-warp
        acc.x += v.x; acc.y += v.y; acc.z += v.z; acc.w += v.w;
    }

    float dn = g_dis[node];
    int c = c4 * 4;
    float4 B  = *(const float4*)&cb[c];
    float4 G  = *(const float4*)&bng[c];
    float4 Be = *(const float4*)&bnb[c];
    float4 M  = *(const float4*)&bnm[c];
    float4 V  = *(const float4*)&bnv[c];
    float4 Ls = ((const float4*)last)[node * 16 + c4];

    float4 o;
    o.x = fmaxf((acc.x * dn + B.x - M.x) * (G.x * rsqrtf(V.x + BN_EPS)) + Be.x, 0.f) + Ls.x;
    o.y = fmaxf((acc.y * dn + B.y - M.y) * (G.y * rsqrtf(V.y + BN_EPS)) + Be.y, 0.f) + Ls.y;
    o.z = fmaxf((acc.z * dn + B.z - M.z) * (G.z * rsqrtf(V.z + BN_EPS)) + Be.z, 0.f) + Ls.z;
    o.w = fmaxf((acc.w * dn + B.w - M.w) * (G.w * rsqrtf(V.w + BN_EPS)) + Be.w, 0.f) + Ls.w;
    ((float4*)out)[node * 16 + c4] = o;
}

// ---------------- launch ----------------
extern "C" void kernel_launch(void* const* d_in, const int* in_sizes, int n_in,
                              void* d_out, int out_size)
{
    const float* x   = (const float*)d_in[0];
    const int*   ei  = (const int*)  d_in[1];
    const float* fcw = (const float*)d_in[2];
    const float* fcb = (const float*)d_in[3];
    const float* cw  = (const float*)d_in[4];
    const float* cb  = (const float*)d_in[5];
    const float* bng = (const float*)d_in[6];
    const float* bnb = (const float*)d_in[7];
    const float* bnm = (const float*)d_in[8];
    const float* bnv = (const float*)d_in[9];
    float* out = (float*)d_out;

    const int* src = ei;         // edge_index[0]
    const int* dst = ei + EE;    // edge_index[1]

    float *ph0, *ph1, *phw;
    cudaGetSymbolAddress((void**)&ph0, g_h0);
    cudaGetSymbolAddress((void**)&ph1, g_h1);
    cudaGetSymbolAddress((void**)&phw, g_hw);

    // CSR build
    zero_k <<<(NN + 255) / 256, 256>>>();
    hist_k <<<(EE + 255) / 256, 256>>>(dst);
    scan1_k<<<(NN + 1023) / 1024, 1024>>>();
    scan2_k<<<1, 128>>>();
    scan3_k<<<(NN + 255) / 256, 256>>>();
    fill_k <<<(EE + 255) / 256, 256>>>(src, dst);

    const int gblocks = (NN + 63) / 64;
    const int ablocks = (NN * 16 + 255) / 256;

    // fc + bn0 + relu
    gemm_k<128, 0><<<gblocks, 256>>>(x, fcw, ph0, fcb, bng, bnb, bnm, bnv);

    // layer 0: transform (x dis) -> aggregate + bn1 + relu + residual
    gemm_k<64, 1><<<gblocks, 256>>>(ph0, cw, phw,
                                    nullptr, nullptr, nullptr, nullptr, nullptr);
    agg_k<<<ablocks, 256>>>(phw, cb, bng + 64, bnb + 64, bnm + 64, bnv + 64,
                            ph0, ph1);

    // layer 1: transform (x dis) -> aggregate + bn2 + relu + residual -> d_out
    gemm_k<64, 1><<<gblocks, 256>>>(ph1, cw + HH * HH, phw,
                                    nullptr, nullptr, nullptr, nullptr, nullptr);
    agg_k<<<ablocks, 256>>>(phw, cb + HH, bng + 128, bnb + 128, bnm + 128, bnv + 128,
                            ph0, out);
}